// round 15
// baseline (speedup 1.0000x reference)
#include <cuda_runtime.h>

// Problem constants (fixed by the dataset problem)
#define BB 2
#define CC 8
#define HH 128
#define WW 128
#define HW (HH * WW)
// patch P=3 -> d=72, window Wn=7 -> n=49

typedef unsigned long long ull;

// Scratch: phi0 = W_phi @ pan, g = W_g @ u, stored [b][y][x][c] as 2x float4 per pixel
__device__ float4 phi0_buf[BB * HW * 2];
__device__ float4 g_buf[BB * HW * 2];
// Partial-softmax scratch: [k = dy+3][field: 0=m 1=denom 2..9=acc][b*HW+pix]
__device__ float part_buf[7][10][BB * HW];

// ---------- packed f32x2 helpers (sm_103a) ----------
__device__ __forceinline__ ull ffma2(ull a, ull b, ull c) {
    ull d;
    asm("fma.rn.f32x2 %0, %1, %2, %3;" : "=l"(d) : "l"(a), "l"(b), "l"(c));
    return d;
}
__device__ __forceinline__ ull fmul2(ull a, ull b) {
    ull d;
    asm("mul.rn.f32x2 %0, %1, %2;" : "=l"(d) : "l"(a), "l"(b));
    return d;
}
__device__ __forceinline__ float2 unpack2(ull v) {
    float2 r;
    asm("mov.b64 {%0, %1}, %2;" : "=f"(r.x), "=f"(r.y) : "l"(v));
    return r;
}
__device__ __forceinline__ ull pack2(float x, float y) {
    ull v;
    asm("mov.b64 %0, {%1, %2};" : "=l"(v) : "f"(x), "f"(y));
    return v;
}

__global__ void precompute_kernel(const float* __restrict__ u,
                                  const float* __restrict__ pan,
                                  const float* __restrict__ Wphi,
                                  const float* __restrict__ Wg) {
    __shared__ float sW[128];  // [0:64) = Wphi, [64:128) = Wg
    int tid = threadIdx.x;
    if (tid < 64) sW[tid] = Wphi[tid];
    else if (tid < 128) sW[tid] = Wg[tid - 64];
    __syncthreads();

    int idx = blockIdx.x * blockDim.x + tid;  // pixel index over b*h*w
    if (idx >= BB * HW) return;
    int b = idx >> 14;
    int pix = idx & (HW - 1);

    const float* pb = pan + b * CC * HW + pix;
    const float* ub = u + b * CC * HW + pix;
    float pv[8], uv[8];
#pragma unroll
    for (int i = 0; i < 8; i++) {
        pv[i] = pb[i * HW];
        uv[i] = ub[i * HW];
    }
    float po[8], go[8];
#pragma unroll
    for (int c = 0; c < 8; c++) {
        float a = 0.f, g = 0.f;
#pragma unroll
        for (int i = 0; i < 8; i++) {
            a += sW[c * 8 + i] * pv[i];
            g += sW[64 + c * 8 + i] * uv[i];
        }
        po[c] = a;
        go[c] = g;
    }
    phi0_buf[idx * 2 + 0] = make_float4(po[0], po[1], po[2], po[3]);
    phi0_buf[idx * 2 + 1] = make_float4(po[4], po[5], po[6], po[7]);
    g_buf[idx * 2 + 0]    = make_float4(go[0], go[1], go[2], go[3]);
    g_buf[idx * 2 + 1]    = make_float4(go[4], go[5], go[6], go[7]);
}

// One block = (16x16 output tile, ONE window row dy, batch b): grid 8x8x14.
// All 256 threads active in both phases; only 2 barriers; no inner loop.
//   logit(y,x,dy,dx) = sum_{i,j in 3x3} S(y+i-1, x+j-1, dy, dx)
//   S(y',x',dy,dx)   = <phi0_pad(y',x'), phi0_pad(y'+dy, x'+dx)>
// logit forced to 0 when window target OOB. Per-pixel PARTIAL softmax over the
// 7 dx of this dy row is written to part_buf; merge_kernel combines the 7 rows.
__global__ __launch_bounds__(256) void attn_kernel() {
    // phi0 tile with halo 4: 24x24 positions, two float4 channel-planes
    __shared__ float4 sPhi0[576];
    __shared__ float4 sPhi1[576];
    // g tile: 16 rows (image rows ty0+dy .. ty0+dy+15) x 22 cols, stride 23
    __shared__ float4 sG0[16 * 23];
    __shared__ float4 sG1[16 * 23];
    // S field for this dy: 7 dx regions of 18x18, row stride 20
    __shared__ float sS[7][18 * 20];

    const int bz = blockIdx.z;
    const int b = bz / 7;
    const int k = bz - b * 7;       // 0..6
    const int dy = k - 3;
    const int ty0 = blockIdx.y * 16;
    const int tx0 = blockIdx.x * 16;
    const int tid = threadIdx.x;

    // warp->row remap for conflict-free box-sum LDS (pairs (rowA, rowA+4): 80 = 16 mod 32)
    const int w = tid >> 5, lane = tid & 31;
    const int tx = lane & 15;
    const int rowA = (w < 4) ? w : (w + 4);
    const int ty = rowA + ((lane >> 4) << 2);

    // ---- load phi0 tile (halo 4, zero pad OOB): 576 pos x 2 halves ----
    for (int i = tid; i < 1152; i += 256) {
        int half = i & 1;
        int pos = i >> 1;
        int r = pos / 24, q = pos - r * 24;
        int gy = ty0 - 4 + r, gx = tx0 - 4 + q;
        float4 v = make_float4(0.f, 0.f, 0.f, 0.f);
        if ((unsigned)gy < HH && (unsigned)gx < WW)
            v = phi0_buf[(b * HW + gy * WW + gx) * 2 + half];
        if (half == 0) sPhi0[pos] = v; else sPhi1[pos] = v;
    }
    // ---- load g tile: rows ty0+dy+r (r 0..15), cols tx0-3+c (c 0..21) ----
    for (int i = tid; i < 704; i += 256) {
        int half = i & 1;
        int pos = i >> 1;
        int r = pos / 22, c = pos - r * 22;
        int gy = ty0 + dy + r, gx = tx0 - 3 + c;
        float4 v = make_float4(0.f, 0.f, 0.f, 0.f);
        if ((unsigned)gy < HH && (unsigned)gx < WW)
            v = g_buf[(b * HW + gy * WW + gx) * 2 + half];
        if (half == 0) sG0[r * 23 + c] = v; else sG1[r * 23 + c] = v;
    }

    // ---- per-thread S items: item0 = tid (all), item1 = tid+256 (tid<68) ----
    // S item (r,q), r,q in 0..17 -> pixel (ty0-1+r, tx0-1+q) -> phi pos (3+r, 3+q)
    const int r0 = tid / 18, q0 = tid - r0 * 18;
    const int p0 = (3 + r0) * 24 + (3 + q0);
    const int d0 = r0 * 20 + q0;
    const int i1 = tid + 256;
    const bool has1 = (i1 < 324);
    const int r1i = i1 / 18;
    const int r1 = has1 ? r1i : r0;
    const int q1 = has1 ? (i1 - r1i * 18) : q0;
    const int p1 = (3 + r1) * 24 + (3 + q1);
    const int d1 = r1 * 20 + q1;

    __syncthreads();  // tiles ready

    // center descriptors, packed f32x2 pairs
    const ulonglong2 c0a = *reinterpret_cast<const ulonglong2*>(&sPhi0[p0]);
    const ulonglong2 c0b = *reinterpret_cast<const ulonglong2*>(&sPhi1[p0]);
    const ulonglong2 c1a = *reinterpret_cast<const ulonglong2*>(&sPhi0[p1]);
    const ulonglong2 c1b = *reinterpret_cast<const ulonglong2*>(&sPhi1[p1]);

    // ---- compute S for all 7 dx of this dy ----
    {
        const int sp0 = p0 + dy * 24 - 3;
#pragma unroll
        for (int t = 0; t < 7; t++) {
            const ulonglong2 na = *reinterpret_cast<const ulonglong2*>(&sPhi0[sp0 + t]);
            const ulonglong2 nb = *reinterpret_cast<const ulonglong2*>(&sPhi1[sp0 + t]);
            ull acc = ffma2(c0a.x, na.x,
                      ffma2(c0a.y, na.y,
                      ffma2(c0b.x, nb.x,
                      fmul2(c0b.y, nb.y))));
            float2 f = unpack2(acc);
            sS[t][d0] = f.x + f.y;
        }
        if (has1) {
            const int sp1 = p1 + dy * 24 - 3;
#pragma unroll
            for (int t = 0; t < 7; t++) {
                const ulonglong2 na = *reinterpret_cast<const ulonglong2*>(&sPhi0[sp1 + t]);
                const ulonglong2 nb = *reinterpret_cast<const ulonglong2*>(&sPhi1[sp1 + t]);
                ull acc = ffma2(c1a.x, na.x,
                          ffma2(c1a.y, na.y,
                          ffma2(c1b.x, nb.x,
                          fmul2(c1b.y, nb.y))));
                float2 f = unpack2(acc);
                sS[t][d1] = f.x + f.y;
            }
        }
    }
    __syncthreads();

    const int py = ty0 + ty;
    const int px = tx0 + tx;

    // ---- 7 box-sums -> logits (0 if window target OOB) ----
    const bool rowOK = (unsigned)(py + dy) < HH;
    const int base = ty * 20 + tx;
    float s[7];
#pragma unroll
    for (int t = 0; t < 7; t++) {
        float v = 0.f;
        if (rowOK && (unsigned)(px + t - 3) < WW) {
            const float* Sx = sS[t];
            v = (Sx[base +  0] + Sx[base +  1]) + (Sx[base +  2] +
                 Sx[base + 20]) + (Sx[base + 21] + Sx[base + 22]) +
                (Sx[base + 40] + Sx[base + 41]) + Sx[base + 42];
        }
        s[t] = v;
    }

    // ---- local softmax partial over this dy row + weighted-g ----
    float mx = s[0];
#pragma unroll
    for (int t = 1; t < 7; t++) mx = fmaxf(mx, s[t]);

    ull acc0 = 0ull, acc1 = 0ull, acc2 = 0ull, acc3 = 0ull;
    float wv[7];
    const int gbase = ty * 23 + tx;  // g local row = ty, col = tx + t
#pragma unroll
    for (int t = 0; t < 7; t++) {
        wv[t] = __expf(s[t] - mx);
        const ull pw = pack2(wv[t], wv[t]);
        const ulonglong2 ga = *reinterpret_cast<const ulonglong2*>(&sG0[gbase + t]);
        const ulonglong2 gb = *reinterpret_cast<const ulonglong2*>(&sG1[gbase + t]);
        acc0 = ffma2(pw, ga.x, acc0);
        acc1 = ffma2(pw, ga.y, acc1);
        acc2 = ffma2(pw, gb.x, acc2);
        acc3 = ffma2(pw, gb.y, acc3);
    }
    const float dsum = ((wv[0] + wv[1]) + (wv[2] + wv[3])) + ((wv[4] + wv[5]) + wv[6]);

    const int pidx = b * HW + py * WW + px;
    const float2 a0 = unpack2(acc0), a1 = unpack2(acc1);
    const float2 a2 = unpack2(acc2), a3 = unpack2(acc3);
    part_buf[k][0][pidx] = mx;
    part_buf[k][1][pidx] = dsum;
    part_buf[k][2][pidx] = a0.x;
    part_buf[k][3][pidx] = a0.y;
    part_buf[k][4][pidx] = a1.x;
    part_buf[k][5][pidx] = a1.y;
    part_buf[k][6][pidx] = a2.x;
    part_buf[k][7][pidx] = a2.y;
    part_buf[k][8][pidx] = a3.x;
    part_buf[k][9][pidx] = a3.y;
}

// Merge the 7 dy-row partials: out = sum_k a_k e^{m_k-M} / sum_k d_k e^{m_k-M}
__global__ __launch_bounds__(256) void merge_kernel(float* __restrict__ out) {
    int i = blockIdx.x * 256 + threadIdx.x;
    if (i >= BB * HW) return;
    const int b = i >> 14;
    const int pix = i & (HW - 1);

    float m[7];
    float M = -1e30f;
#pragma unroll
    for (int k = 0; k < 7; k++) {
        m[k] = part_buf[k][0][i];
        M = fmaxf(M, m[k]);
    }
    float D = 0.f;
    float A[8] = {0.f, 0.f, 0.f, 0.f, 0.f, 0.f, 0.f, 0.f};
#pragma unroll
    for (int k = 0; k < 7; k++) {
        const float e = __expf(m[k] - M);
        D += part_buf[k][1][i] * e;
#pragma unroll
        for (int c = 0; c < 8; c++)
            A[c] += part_buf[k][2 + c][i] * e;
    }
    const float inv = 1.f / D;
    float* ob = out + b * CC * HW + pix;
#pragma unroll
    for (int c = 0; c < 8; c++)
        ob[c * HW] = A[c] * inv;
}

extern "C" void kernel_launch(void* const* d_in, const int* in_sizes, int n_in,
                              void* d_out, int out_size) {
    const float* u    = (const float*)d_in[0];
    const float* pan  = (const float*)d_in[1];
    const float* Wphi = (const float*)d_in[2];
    const float* Wg   = (const float*)d_in[3];
    float* out = (float*)d_out;

    // phase 1: 1x1 convs into channel-contiguous scratch
    precompute_kernel<<<(BB * HW + 255) / 256, 256>>>(u, pan, Wphi, Wg);

    // phase 2: window attention partials, one dy row per block (8x8x14 = 896 blocks)
    dim3 grid(WW / 16, HH / 16, BB * 7);
    attn_kernel<<<grid, 256>>>();

    // phase 3: merge the 7 partials per pixel
    merge_kernel<<<(BB * HW + 255) / 256, 256>>>(out);
}